// round 12
// baseline (speedup 1.0000x reference)
#include <cuda_runtime.h>
#include <cstdint>
#include <math.h>

// ---------------------------------------------------------------------------
// Scratch (static device globals — no runtime allocation)
// ---------------------------------------------------------------------------
__device__ float g_h0 [8192u * 2048u];   // layer0 h, full precision
__device__ float g_h0r[8192u * 2048u];   // layer0 h, tf32-rounded
__device__ float g_h1r[8192u * 1024u];   // layer1 h, tf32-rounded
__device__ float g_pre[8192u * 2048u];   // pre-LN buffer
__device__ float g_err[8192u * 4096u];   // error, tf32-rounded
__device__ float g_xr [8192u * 4096u];   // x, tf32-rounded
__device__ float g_wts[20u * 1024u * 1024u]; // rounded weights
__device__ float g_prec2[4096];

#define W_GEN0 0u                       // 4096*2048
#define W_REC0 (8u*1024u*1024u)         // 2048*4096
#define W_GEN1 (16u*1024u*1024u)        // 2048*1024
#define W_REC1 (18u*1024u*1024u)        // 1024*2048

// ---------------------------------------------------------------------------
// Helpers
// ---------------------------------------------------------------------------
__device__ __forceinline__ uint32_t f2tf32(float x) {
    uint32_t r;
    asm("cvt.rna.tf32.f32 %0, %1;" : "=r"(r) : "f"(x));
    return r;
}
__device__ __forceinline__ float roundtf(float x) { return __uint_as_float(f2tf32(x)); }

__device__ __forceinline__ void mma_tf32(float* c, const uint32_t* a, const uint32_t* b) {
    asm volatile(
        "mma.sync.aligned.m16n8k8.row.col.f32.tf32.tf32.f32 "
        "{%0,%1,%2,%3}, {%4,%5,%6,%7}, {%8,%9}, {%0,%1,%2,%3};\n"
        : "+f"(c[0]), "+f"(c[1]), "+f"(c[2]), "+f"(c[3])
        : "r"(a[0]), "r"(a[1]), "r"(a[2]), "r"(a[3]), "r"(b[0]), "r"(b[1]));
}

__device__ __forceinline__ void cp16(uint32_t dst_smem, const void* src) {
    asm volatile("cp.async.cg.shared.global [%0], [%1], 16;" :: "r"(dst_smem), "l"(src));
}
__device__ __forceinline__ void cp_commit() { asm volatile("cp.async.commit_group;"); }
template <int N>
__device__ __forceinline__ void cp_wait() { asm volatile("cp.async.wait_group %0;" :: "n"(N)); }

// ---------------------------------------------------------------------------
// Elementwise tf32 rounding (weights, x)
// ---------------------------------------------------------------------------
__global__ void __launch_bounds__(256) round_kernel(
    const float* __restrict__ in, float* __restrict__ out, int n4)
{
    int i = blockIdx.x * blockDim.x + threadIdx.x;
    if (i < n4) {
        float4 v = reinterpret_cast<const float4*>(in)[i];
        float4 o;
        o.x = roundtf(v.x); o.y = roundtf(v.y);
        o.z = roundtf(v.z); o.w = roundtf(v.w);
        reinterpret_cast<float4*>(out)[i] = o;
    }
}

// ---------------------------------------------------------------------------
// prec2 = softplus(log_prec)^2
// ---------------------------------------------------------------------------
__global__ void prec2_kernel(const float* __restrict__ lp, float* __restrict__ out, int n) {
    int i = blockIdx.x * blockDim.x + threadIdx.x;
    if (i < n) {
        float v = lp[i];
        float sp = (v > 20.f) ? v : log1pf(expf(v));
        out[i] = sp * sp;
    }
}

// ---------------------------------------------------------------------------
// Row LayerNorm. Writes full-precision dst and tf32-rounded dstr.
// ---------------------------------------------------------------------------
template <int H>
__global__ void __launch_bounds__(256) ln_kernel(
    const float* __restrict__ src, float* __restrict__ dst, float* __restrict__ dstr,
    const float* __restrict__ gam, const float* __restrict__ bet)
{
    constexpr int V = H / (4 * 256);
    int row = blockIdx.x;
    const float4* s = reinterpret_cast<const float4*>(src + (size_t)row * H);
    float4* d  = reinterpret_cast<float4*>(dst  + (size_t)row * H);
    float4* dr = reinterpret_cast<float4*>(dstr + (size_t)row * H);

    float4 v[V];
    float sum = 0.f, sq = 0.f;
#pragma unroll
    for (int i = 0; i < V; i++) {
        v[i] = s[threadIdx.x + i * 256];
        sum += v[i].x + v[i].y + v[i].z + v[i].w;
        sq  += v[i].x * v[i].x + v[i].y * v[i].y + v[i].z * v[i].z + v[i].w * v[i].w;
    }
#pragma unroll
    for (int o = 16; o > 0; o >>= 1) {
        sum += __shfl_xor_sync(0xffffffffu, sum, o);
        sq  += __shfl_xor_sync(0xffffffffu, sq,  o);
    }
    __shared__ float sS[8], sQ[8];
    int w = threadIdx.x >> 5, l = threadIdx.x & 31;
    if (l == 0) { sS[w] = sum; sQ[w] = sq; }
    __syncthreads();
    if (threadIdx.x == 0) {
        float ts = 0.f, tq = 0.f;
#pragma unroll
        for (int i = 0; i < 8; i++) { ts += sS[i]; tq += sQ[i]; }
        sS[0] = ts; sQ[0] = tq;
    }
    __syncthreads();
    float mu  = sS[0] * (1.f / H);
    float var = sQ[0] * (1.f / H) - mu * mu;
    float inv = rsqrtf(var + 1e-5f);
#pragma unroll
    for (int i = 0; i < V; i++) {
        int ci = threadIdx.x + i * 256;
        float4 g4 = reinterpret_cast<const float4*>(gam)[ci];
        float4 b4 = reinterpret_cast<const float4*>(bet)[ci];
        float4 o;
        o.x = (v[i].x - mu) * inv * g4.x + b4.x;
        o.y = (v[i].y - mu) * inv * g4.y + b4.y;
        o.z = (v[i].z - mu) * inv * g4.z + b4.z;
        o.w = (v[i].w - mu) * inv * g4.w + b4.w;
        d[ci] = o;
        float4 r;
        r.x = roundtf(o.x); r.y = roundtf(o.y);
        r.z = roundtf(o.z); r.w = roundtf(o.w);
        dr[ci] = r;
    }
}

// ---------------------------------------------------------------------------
// TF32 mma.sync GEMM, 128x256 CTA tile, 64x64 warp tiles (2x4 warps),
// BK=32 stages, 3-stage cp.async pipeline. Inputs pre-rounded to tf32.
//   BT=true : B(k,n) = W[n,k]   (W row-major [N,K])
//   BT=false: B(k,n) = W[k,n]   (W row-major [K,N])
// MODE 0: out = acc + bias[n]
// MODE 1: out = roundtf((X - (acc + bias[n])) * prec2[n])
// MODE 2: out = X + 0.2f * acc
// Requires M%128==0, N%256==0, K%32==0.
// ---------------------------------------------------------------------------
template <bool BT, int MODE>
__global__ void __launch_bounds__(256, 1) gemm_tf32(
    const float* __restrict__ A, const float* __restrict__ W,
    const float* __restrict__ bias, const float* __restrict__ X,
    const float* __restrict__ prec2, float* __restrict__ OUT,
    int M, int N, int K)
{
    constexpr int S    = 3;      // pipeline stages
    constexpr int AROW = 36;     // 32 k-floats + 4 pad (144B rows)
    constexpr int BRN  = 264;    // NN path: 256 n-floats + 8 pad
    constexpr int A_FLOATS = 128 * AROW;            // 4608 per stage
    constexpr int B_FLOATS = BT ? 256 * AROW : 32 * BRN;  // 9216 / 8448

    extern __shared__ float sm[];
    float* Asm = sm;                       // [S][128][AROW]
    float* Bsm = sm + S * A_FLOATS;

    const uint32_t sA = (uint32_t)__cvta_generic_to_shared(Asm);
    const uint32_t sB = (uint32_t)__cvta_generic_to_shared(Bsm);

    const int tid  = threadIdx.x;
    const int lane = tid & 31;
    const int warp = tid >> 5;
    const int wm = warp >> 2;          // 0..1  (64-row band)
    const int wn = warp & 3;           // 0..3  (64-col band)
    const int gid = lane >> 2, tig = lane & 3;
    const int M0 = blockIdx.y * 128, N0 = blockIdx.x * 256;

    float acc[4][8][4];
#pragma unroll
    for (int i = 0; i < 4; i++)
#pragma unroll
        for (int j = 0; j < 8; j++)
#pragma unroll
            for (int k = 0; k < 4; k++) acc[i][j][k] = 0.f;

    const int KT = K / 32;

    // one stage: A = 1024 cp16 (4/thread), B = 2048 cp16 (8/thread)
    auto ldgsts = [&](int kt, int st) {
#pragma unroll
        for (int i = 0; i < 4; i++) {
            int c   = tid + 256 * i;           // 0..1023
            int row = c >> 3, kv = c & 7;
            cp16(sA + (uint32_t)(st * A_FLOATS + row * AROW + kv * 4) * 4u,
                 A + (size_t)(M0 + row) * K + kt * 32 + kv * 4);
        }
        if (BT) {
#pragma unroll
            for (int i = 0; i < 8; i++) {
                int c   = tid + 256 * i;       // 0..2047
                int row = c >> 3, kv = c & 7;
                cp16(sB + (uint32_t)(st * B_FLOATS + row * AROW + kv * 4) * 4u,
                     W + (size_t)(N0 + row) * K + kt * 32 + kv * 4);
            }
        } else {
#pragma unroll
            for (int i = 0; i < 8; i++) {
                int c  = tid + 256 * i;        // 0..2047
                int kr = c >> 6, nv = c & 63;  // k-row 0..31, nvec 0..63
                cp16(sB + (uint32_t)(st * B_FLOATS + kr * BRN + nv * 4) * 4u,
                     W + (size_t)(kt * 32 + kr) * N + N0 + nv * 4);
            }
        }
    };

    // prologue: fill 2 stages
    ldgsts(0, 0); cp_commit();
    ldgsts(1, 1); cp_commit();

    for (int kt = 0; kt < KT; kt++) {
        cp_wait<1>();
        __syncthreads();

        int nk = kt + 2;
        if (nk < KT) ldgsts(nk, nk % S);
        cp_commit();

        const uint32_t* Ast = (const uint32_t*)(Asm + (kt % S) * A_FLOATS);
        const uint32_t* Bst = (const uint32_t*)(Bsm + (kt % S) * B_FLOATS);

#pragma unroll
        for (int ks = 0; ks < 4; ks++) {
            const int k0 = ks * 8;
            uint32_t af[4][4], bf[8][2];
#pragma unroll
            for (int mm = 0; mm < 4; mm++) {
                int r = wm * 64 + mm * 16 + gid;
                af[mm][0] = Ast[(r    ) * AROW + k0 + tig    ];
                af[mm][1] = Ast[(r + 8) * AROW + k0 + tig    ];
                af[mm][2] = Ast[(r    ) * AROW + k0 + tig + 4];
                af[mm][3] = Ast[(r + 8) * AROW + k0 + tig + 4];
            }
#pragma unroll
            for (int nn = 0; nn < 8; nn++) {
                int cN = wn * 64 + nn * 8 + gid;
                if (BT) {
                    bf[nn][0] = Bst[cN * AROW + k0 + tig    ];
                    bf[nn][1] = Bst[cN * AROW + k0 + tig + 4];
                } else {
                    bf[nn][0] = Bst[(k0 + tig    ) * BRN + cN];
                    bf[nn][1] = Bst[(k0 + tig + 4) * BRN + cN];
                }
            }
#pragma unroll
            for (int mm = 0; mm < 4; mm++)
#pragma unroll
                for (int nn = 0; nn < 8; nn++)
                    mma_tf32(acc[mm][nn], af[mm], bf[nn]);
        }
    }

    // epilogue
#pragma unroll
    for (int mm = 0; mm < 4; mm++) {
        int r0 = M0 + wm * 64 + mm * 16 + gid;
#pragma unroll
        for (int nn = 0; nn < 8; nn++) {
            int c = N0 + wn * 64 + nn * 8 + 2 * tig;
#pragma unroll
            for (int h = 0; h < 2; h++) {
                int r = r0 + h * 8;
                size_t off = (size_t)r * N + c;
                float v0 = acc[mm][nn][2 * h + 0];
                float v1 = acc[mm][nn][2 * h + 1];
                if (MODE == 0) {
                    v0 += bias[c];
                    v1 += bias[c + 1];
                } else if (MODE == 1) {
                    float2 xv = *(const float2*)(X + off);
                    v0 = roundtf((xv.x - (v0 + bias[c]))     * prec2[c]);
                    v1 = roundtf((xv.y - (v1 + bias[c + 1])) * prec2[c + 1]);
                } else {
                    float2 xv = *(const float2*)(X + off);
                    v0 = xv.x + 0.2f * v0;
                    v1 = xv.y + 0.2f * v1;
                }
                float2 o; o.x = v0; o.y = v1;
                *(float2*)(OUT + off) = o;
            }
        }
    }
}

// ---------------------------------------------------------------------------
// Launch sequence (graph-capturable: kernel launches only)
// ---------------------------------------------------------------------------
extern "C" void kernel_launch(void* const* d_in, const int* in_sizes, int n_in,
                              void* d_out, int out_size)
{
    const float* x      = (const float*)d_in[0];
    const float* gen_w0 = (const float*)d_in[1];
    const float* gen_b0 = (const float*)d_in[2];
    const float* rec_w0 = (const float*)d_in[3];
    const float* rec_b0 = (const float*)d_in[4];
    const float* lp0    = (const float*)d_in[5];
    const float* ln_g0  = (const float*)d_in[6];
    const float* ln_b0  = (const float*)d_in[7];
    const float* gen_w1 = (const float*)d_in[8];
    const float* gen_b1 = (const float*)d_in[9];
    const float* rec_w1 = (const float*)d_in[10];
    const float* rec_b1 = (const float*)d_in[11];
    const float* lp1    = (const float*)d_in[12];
    const float* ln_g1  = (const float*)d_in[13];
    const float* ln_b1  = (const float*)d_in[14];
    float* out = (float*)d_out;

    float *h0, *h0r, *h1r, *pre, *err, *xr, *wts, *pr2;
    cudaGetSymbolAddress((void**)&h0,  g_h0);
    cudaGetSymbolAddress((void**)&h0r, g_h0r);
    cudaGetSymbolAddress((void**)&h1r, g_h1r);
    cudaGetSymbolAddress((void**)&pre, g_pre);
    cudaGetSymbolAddress((void**)&err, g_err);
    cudaGetSymbolAddress((void**)&xr,  g_xr);
    cudaGetSymbolAddress((void**)&wts, g_wts);
    cudaGetSymbolAddress((void**)&pr2, g_prec2);

    float* gen_w0r = wts + W_GEN0;
    float* rec_w0r = wts + W_REC0;
    float* gen_w1r = wts + W_GEN1;
    float* rec_w1r = wts + W_REC1;

    // dynamic smem: BT = 3*(4608+9216)*4 = 165,888 B; NN = 3*(4608+8448)*4 = 156,672 B
    const int SM_BT = 3 * (128 * 36 + 256 * 36) * 4;
    const int SM_NN = 3 * (128 * 36 + 32 * 264) * 4;
    cudaFuncSetAttribute(gemm_tf32<true, 0>,  cudaFuncAttributeMaxDynamicSharedMemorySize, SM_BT);
    cudaFuncSetAttribute(gemm_tf32<true, 1>,  cudaFuncAttributeMaxDynamicSharedMemorySize, SM_BT);
    cudaFuncSetAttribute(gemm_tf32<false, 2>, cudaFuncAttributeMaxDynamicSharedMemorySize, SM_NN);

    const int B = 8192;
    dim3 blk(256);

    // one-time rounding of weights and x (bit-identical to consume-side cvt)
    round_kernel<<<(4096 * 2048 / 4) / 256, blk>>>(gen_w0, gen_w0r, 4096 * 2048 / 4);
    round_kernel<<<(2048 * 4096 / 4) / 256, blk>>>(rec_w0, rec_w0r, 2048 * 4096 / 4);
    round_kernel<<<(2048 * 1024 / 4) / 256, blk>>>(gen_w1, gen_w1r, 2048 * 1024 / 4);
    round_kernel<<<(1024 * 2048 / 4) / 256, blk>>>(rec_w1, rec_w1r, 1024 * 2048 / 4);
    round_kernel<<<(B * 4096 / 4) / 256, blk>>>(x, xr, B * 4096 / 4);

    // ---- layer 0: in=4096, hid=2048 ----
    prec2_kernel<<<4096 / 256, blk>>>(lp0, pr2, 4096);
    gemm_tf32<true, 0><<<dim3(2048 / 256, B / 128), blk, SM_BT>>>(
        xr, rec_w0r, rec_b0, nullptr, nullptr, pre, B, 2048, 4096);
    ln_kernel<2048><<<B, blk>>>(pre, h0, h0r, ln_g0, ln_b0);
    for (int it = 0; it < 3; it++) {
        gemm_tf32<true, 1><<<dim3(4096 / 256, B / 128), blk, SM_BT>>>(
            h0r, gen_w0r, gen_b0, x, pr2, err, B, 4096, 2048);
        gemm_tf32<false, 2><<<dim3(2048 / 256, B / 128), blk, SM_NN>>>(
            err, gen_w0r, nullptr, h0, nullptr, pre, B, 2048, 4096);
        ln_kernel<2048><<<B, blk>>>(pre, h0, h0r, ln_g0, ln_b0);
    }

    // ---- layer 1: in=2048, hid=1024 ----
    prec2_kernel<<<2048 / 256, blk>>>(lp1, pr2, 2048);
    gemm_tf32<true, 0><<<dim3(1024 / 256, B / 128), blk, SM_BT>>>(
        h0r, rec_w1r, rec_b1, nullptr, nullptr, pre, B, 1024, 2048);
    ln_kernel<1024><<<B, blk>>>(pre, out, h1r, ln_g1, ln_b1);
    for (int it = 0; it < 3; it++) {
        gemm_tf32<true, 1><<<dim3(2048 / 256, B / 128), blk, SM_BT>>>(
            h1r, gen_w1r, gen_b1, h0, pr2, err, B, 2048, 1024);
        gemm_tf32<false, 2><<<dim3(1024 / 256, B / 128), blk, SM_NN>>>(
            err, gen_w1r, nullptr, out, nullptr, pre, B, 1024, 2048);
        ln_kernel<1024><<<B, blk>>>(pre, out, h1r, ln_g1, ln_b1);
    }
}

// round 14
// speedup vs baseline: 1.0355x; 1.0355x over previous
#include <cuda_runtime.h>
#include <cstdint>
#include <math.h>

// ---------------------------------------------------------------------------
// Scratch (static device globals — no runtime allocation)
// ---------------------------------------------------------------------------
__device__ float g_h0 [8192u * 2048u];   // layer0 h, full precision
__device__ float g_h0r[8192u * 2048u];   // layer0 h, tf32-rounded
__device__ float g_h1r[8192u * 1024u];   // layer1 h, tf32-rounded
__device__ float g_pre[8192u * 2048u];   // pre-LN buffer
__device__ float g_err[8192u * 4096u];   // error, tf32-rounded
__device__ float g_xr [8192u * 4096u];   // x, tf32-rounded
__device__ float g_wts[20u * 1024u * 1024u]; // rounded weights
__device__ float g_prec2[4096];

#define W_GEN0 0u                       // 4096*2048
#define W_REC0 (8u*1024u*1024u)         // 2048*4096
#define W_GEN1 (16u*1024u*1024u)        // 2048*1024
#define W_REC1 (18u*1024u*1024u)        // 1024*2048

// ---------------------------------------------------------------------------
// Helpers
// ---------------------------------------------------------------------------
__device__ __forceinline__ uint32_t f2tf32(float x) {
    uint32_t r;
    asm("cvt.rna.tf32.f32 %0, %1;" : "=r"(r) : "f"(x));
    return r;
}
__device__ __forceinline__ float roundtf(float x) { return __uint_as_float(f2tf32(x)); }

__device__ __forceinline__ void mma_tf32(float* c, const uint32_t* a, const uint32_t* b) {
    asm volatile(
        "mma.sync.aligned.m16n8k8.row.col.f32.tf32.tf32.f32 "
        "{%0,%1,%2,%3}, {%4,%5,%6,%7}, {%8,%9}, {%0,%1,%2,%3};\n"
        : "+f"(c[0]), "+f"(c[1]), "+f"(c[2]), "+f"(c[3])
        : "r"(a[0]), "r"(a[1]), "r"(a[2]), "r"(a[3]), "r"(b[0]), "r"(b[1]));
}

__device__ __forceinline__ void cp16(uint32_t dst_smem, const void* src) {
    asm volatile("cp.async.cg.shared.global [%0], [%1], 16;" :: "r"(dst_smem), "l"(src));
}
__device__ __forceinline__ void cp_commit() { asm volatile("cp.async.commit_group;"); }
template <int N>
__device__ __forceinline__ void cp_wait() { asm volatile("cp.async.wait_group %0;" :: "n"(N)); }

// ---------------------------------------------------------------------------
// Elementwise tf32 rounding (weights, x)
// ---------------------------------------------------------------------------
__global__ void __launch_bounds__(256) round_kernel(
    const float* __restrict__ in, float* __restrict__ out, int n4)
{
    int i = blockIdx.x * blockDim.x + threadIdx.x;
    if (i < n4) {
        float4 v = reinterpret_cast<const float4*>(in)[i];
        float4 o;
        o.x = roundtf(v.x); o.y = roundtf(v.y);
        o.z = roundtf(v.z); o.w = roundtf(v.w);
        reinterpret_cast<float4*>(out)[i] = o;
    }
}

// ---------------------------------------------------------------------------
// prec2 = softplus(log_prec)^2
// ---------------------------------------------------------------------------
__global__ void prec2_kernel(const float* __restrict__ lp, float* __restrict__ out, int n) {
    int i = blockIdx.x * blockDim.x + threadIdx.x;
    if (i < n) {
        float v = lp[i];
        float sp = (v > 20.f) ? v : log1pf(expf(v));
        out[i] = sp * sp;
    }
}

// ---------------------------------------------------------------------------
// Row LayerNorm. Writes full-precision dst and tf32-rounded dstr.
// ---------------------------------------------------------------------------
template <int H>
__global__ void __launch_bounds__(256) ln_kernel(
    const float* __restrict__ src, float* __restrict__ dst, float* __restrict__ dstr,
    const float* __restrict__ gam, const float* __restrict__ bet)
{
    constexpr int V = H / (4 * 256);
    int row = blockIdx.x;
    const float4* s = reinterpret_cast<const float4*>(src + (size_t)row * H);
    float4* d  = reinterpret_cast<float4*>(dst  + (size_t)row * H);
    float4* dr = reinterpret_cast<float4*>(dstr + (size_t)row * H);

    float4 v[V];
    float sum = 0.f, sq = 0.f;
#pragma unroll
    for (int i = 0; i < V; i++) {
        v[i] = s[threadIdx.x + i * 256];
        sum += v[i].x + v[i].y + v[i].z + v[i].w;
        sq  += v[i].x * v[i].x + v[i].y * v[i].y + v[i].z * v[i].z + v[i].w * v[i].w;
    }
#pragma unroll
    for (int o = 16; o > 0; o >>= 1) {
        sum += __shfl_xor_sync(0xffffffffu, sum, o);
        sq  += __shfl_xor_sync(0xffffffffu, sq,  o);
    }
    __shared__ float sS[8], sQ[8];
    int w = threadIdx.x >> 5, l = threadIdx.x & 31;
    if (l == 0) { sS[w] = sum; sQ[w] = sq; }
    __syncthreads();
    if (threadIdx.x == 0) {
        float ts = 0.f, tq = 0.f;
#pragma unroll
        for (int i = 0; i < 8; i++) { ts += sS[i]; tq += sQ[i]; }
        sS[0] = ts; sQ[0] = tq;
    }
    __syncthreads();
    float mu  = sS[0] * (1.f / H);
    float var = sQ[0] * (1.f / H) - mu * mu;
    float inv = rsqrtf(var + 1e-5f);
#pragma unroll
    for (int i = 0; i < V; i++) {
        int ci = threadIdx.x + i * 256;
        float4 g4 = reinterpret_cast<const float4*>(gam)[ci];
        float4 b4 = reinterpret_cast<const float4*>(bet)[ci];
        float4 o;
        o.x = (v[i].x - mu) * inv * g4.x + b4.x;
        o.y = (v[i].y - mu) * inv * g4.y + b4.y;
        o.z = (v[i].z - mu) * inv * g4.z + b4.z;
        o.w = (v[i].w - mu) * inv * g4.w + b4.w;
        d[ci] = o;
        float4 r;
        r.x = roundtf(o.x); r.y = roundtf(o.y);
        r.z = roundtf(o.z); r.w = roundtf(o.w);
        dr[ci] = r;
    }
}

// ---------------------------------------------------------------------------
// TF32 mma.sync GEMM, 128x128 tile, 64x32 warp tiles (2x4 warps), BK=32,
// 3-stage cp.async pipeline, explicit ks-level register double-buffering of
// fragments. Inputs pre-rounded to tf32 -> mainloop is pure LDS+MMA.
//   BT=true : B(k,n) = W[n,k]   (W row-major [N,K])
//   BT=false: B(k,n) = W[k,n]   (W row-major [K,N])
// MODE 0: out = acc + bias[n]
// MODE 1: out = roundtf((X - (acc + bias[n])) * prec2[n])
// MODE 2: out = X + 0.2f * acc
// Requires M%128==0, N%128==0, K%32==0.
// ---------------------------------------------------------------------------
template <bool BT, int MODE>
__global__ void __launch_bounds__(256, 2) gemm_tf32(
    const float* __restrict__ A, const float* __restrict__ W,
    const float* __restrict__ bias, const float* __restrict__ X,
    const float* __restrict__ prec2, float* __restrict__ OUT,
    int M, int N, int K)
{
    constexpr int S    = 3;      // pipeline stages
    constexpr int AROW = 36;     // 32 k-floats + 4 pad (144B rows)
    constexpr int BRN  = 136;    // NN path: 128 n-floats + 8 pad
    constexpr int A_FLOATS = 128 * AROW;            // 4608 per stage
    constexpr int B_FLOATS = BT ? 128 * AROW : 32 * BRN;

    extern __shared__ float sm[];
    float* Asm = sm;                       // [S][128][AROW]
    float* Bsm = sm + S * A_FLOATS;

    const uint32_t sA = (uint32_t)__cvta_generic_to_shared(Asm);
    const uint32_t sB = (uint32_t)__cvta_generic_to_shared(Bsm);

    const int tid  = threadIdx.x;
    const int lane = tid & 31;
    const int warp = tid >> 5;
    const int wm = warp >> 2;
    const int wn = warp & 3;
    const int gid = lane >> 2, tig = lane & 3;
    const int M0 = blockIdx.y * 128, N0 = blockIdx.x * 128;

    float acc[4][4][4];
#pragma unroll
    for (int i = 0; i < 4; i++)
#pragma unroll
        for (int j = 0; j < 4; j++)
#pragma unroll
            for (int k = 0; k < 4; k++) acc[i][j][k] = 0.f;

    const int KT = K / 32;

    // one stage = 128 rows x 32 floats for A (1024 cp16 = 4/thread), same for B
    auto ldgsts = [&](int kt, int st) {
#pragma unroll
        for (int i = 0; i < 4; i++) {
            int c   = tid + 256 * i;           // 0..1023
            int row = c >> 3, kv = c & 7;
            cp16(sA + (uint32_t)(st * A_FLOATS + row * AROW + kv * 4) * 4u,
                 A + (size_t)(M0 + row) * K + kt * 32 + kv * 4);
        }
        if (BT) {
#pragma unroll
            for (int i = 0; i < 4; i++) {
                int c   = tid + 256 * i;
                int row = c >> 3, kv = c & 7;
                cp16(sB + (uint32_t)(st * B_FLOATS + row * AROW + kv * 4) * 4u,
                     W + (size_t)(N0 + row) * K + kt * 32 + kv * 4);
            }
        } else {
#pragma unroll
            for (int i = 0; i < 4; i++) {
                int c  = tid + 256 * i;
                int kr = c >> 5, nv = c & 31;  // k-row 0..31, nvec 0..31
                cp16(sB + (uint32_t)(st * B_FLOATS + kr * BRN + nv * 4) * 4u,
                     W + (size_t)(kt * 32 + kr) * N + N0 + nv * 4);
            }
        }
    };

    // prologue: fill S-1 = 2 stages
    ldgsts(0, 0); cp_commit();
    ldgsts(1, 1); cp_commit();

    // double-buffered fragment registers
    uint32_t af[2][4][4], bf[2][4][2];

    for (int kt = 0; kt < KT; kt++) {
        cp_wait<1>();
        __syncthreads();

        int nk = kt + 2;
        if (nk < KT) ldgsts(nk, nk % S);
        cp_commit();

        const uint32_t* Ast = (const uint32_t*)(Asm + (kt % S) * A_FLOATS);
        const uint32_t* Bst = (const uint32_t*)(Bsm + (kt % S) * B_FLOATS);

        // fragment load for one ks group into buffer b
        auto ldfrag = [&](int ks, int b) {
            const int k0 = ks * 8;
#pragma unroll
            for (int mm = 0; mm < 4; mm++) {
                int r = wm * 64 + mm * 16 + gid;
                af[b][mm][0] = Ast[(r    ) * AROW + k0 + tig    ];
                af[b][mm][1] = Ast[(r + 8) * AROW + k0 + tig    ];
                af[b][mm][2] = Ast[(r    ) * AROW + k0 + tig + 4];
                af[b][mm][3] = Ast[(r + 8) * AROW + k0 + tig + 4];
            }
#pragma unroll
            for (int nn = 0; nn < 4; nn++) {
                int cN = wn * 32 + nn * 8 + gid;
                if (BT) {
                    bf[b][nn][0] = Bst[cN * AROW + k0 + tig    ];
                    bf[b][nn][1] = Bst[cN * AROW + k0 + tig + 4];
                } else {
                    bf[b][nn][0] = Bst[(k0 + tig    ) * BRN + cN];
                    bf[b][nn][1] = Bst[(k0 + tig + 4) * BRN + cN];
                }
            }
        };

        ldfrag(0, 0);
#pragma unroll
        for (int ks = 0; ks < 4; ks++) {
            if (ks < 3) ldfrag(ks + 1, (ks + 1) & 1);   // prefetch next group
            const int b = ks & 1;
#pragma unroll
            for (int mm = 0; mm < 4; mm++)
#pragma unroll
                for (int nn = 0; nn < 4; nn++)
                    mma_tf32(acc[mm][nn], af[b][mm], bf[b][nn]);
        }
    }

    // epilogue
#pragma unroll
    for (int mm = 0; mm < 4; mm++) {
        int r0 = M0 + wm * 64 + mm * 16 + gid;
#pragma unroll
        for (int nn = 0; nn < 4; nn++) {
            int c = N0 + wn * 32 + nn * 8 + 2 * tig;
#pragma unroll
            for (int h = 0; h < 2; h++) {
                int r = r0 + h * 8;
                size_t off = (size_t)r * N + c;
                float v0 = acc[mm][nn][2 * h + 0];
                float v1 = acc[mm][nn][2 * h + 1];
                if (MODE == 0) {
                    v0 += bias[c];
                    v1 += bias[c + 1];
                } else if (MODE == 1) {
                    float2 xv = *(const float2*)(X + off);
                    v0 = roundtf((xv.x - (v0 + bias[c]))     * prec2[c]);
                    v1 = roundtf((xv.y - (v1 + bias[c + 1])) * prec2[c + 1]);
                } else {
                    float2 xv = *(const float2*)(X + off);
                    v0 = xv.x + 0.2f * v0;
                    v1 = xv.y + 0.2f * v1;
                }
                float2 o; o.x = v0; o.y = v1;
                *(float2*)(OUT + off) = o;
            }
        }
    }
}

// ---------------------------------------------------------------------------
// Launch sequence (graph-capturable: kernel launches only)
// ---------------------------------------------------------------------------
extern "C" void kernel_launch(void* const* d_in, const int* in_sizes, int n_in,
                              void* d_out, int out_size)
{
    const float* x      = (const float*)d_in[0];
    const float* gen_w0 = (const float*)d_in[1];
    const float* gen_b0 = (const float*)d_in[2];
    const float* rec_w0 = (const float*)d_in[3];
    const float* rec_b0 = (const float*)d_in[4];
    const float* lp0    = (const float*)d_in[5];
    const float* ln_g0  = (const float*)d_in[6];
    const float* ln_b0  = (const float*)d_in[7];
    const float* gen_w1 = (const float*)d_in[8];
    const float* gen_b1 = (const float*)d_in[9];
    const float* rec_w1 = (const float*)d_in[10];
    const float* rec_b1 = (const float*)d_in[11];
    const float* lp1    = (const float*)d_in[12];
    const float* ln_g1  = (const float*)d_in[13];
    const float* ln_b1  = (const float*)d_in[14];
    float* out = (float*)d_out;

    float *h0, *h0r, *h1r, *pre, *err, *xr, *wts, *pr2;
    cudaGetSymbolAddress((void**)&h0,  g_h0);
    cudaGetSymbolAddress((void**)&h0r, g_h0r);
    cudaGetSymbolAddress((void**)&h1r, g_h1r);
    cudaGetSymbolAddress((void**)&pre, g_pre);
    cudaGetSymbolAddress((void**)&err, g_err);
    cudaGetSymbolAddress((void**)&xr,  g_xr);
    cudaGetSymbolAddress((void**)&wts, g_wts);
    cudaGetSymbolAddress((void**)&pr2, g_prec2);

    float* gen_w0r = wts + W_GEN0;
    float* rec_w0r = wts + W_REC0;
    float* gen_w1r = wts + W_GEN1;
    float* rec_w1r = wts + W_REC1;

    // dynamic smem: BT = 3*(4608*2)*4 = 110,592 B; NN = 3*(4608+4352)*4 = 107,520 B
    const int SM_BT = 3 * (128 * 36 * 2) * 4;
    const int SM_NN = 3 * (128 * 36 + 32 * 136) * 4;
    cudaFuncSetAttribute(gemm_tf32<true, 0>,  cudaFuncAttributeMaxDynamicSharedMemorySize, SM_BT);
    cudaFuncSetAttribute(gemm_tf32<true, 1>,  cudaFuncAttributeMaxDynamicSharedMemorySize, SM_BT);
    cudaFuncSetAttribute(gemm_tf32<false, 2>, cudaFuncAttributeMaxDynamicSharedMemorySize, SM_NN);

    const int B = 8192;
    dim3 blk(256);

    // one-time rounding of weights and x (bit-identical to consume-side cvt)
    round_kernel<<<(4096 * 2048 / 4) / 256, blk>>>(gen_w0, gen_w0r, 4096 * 2048 / 4);
    round_kernel<<<(2048 * 4096 / 4) / 256, blk>>>(rec_w0, rec_w0r, 2048 * 4096 / 4);
    round_kernel<<<(2048 * 1024 / 4) / 256, blk>>>(gen_w1, gen_w1r, 2048 * 1024 / 4);
    round_kernel<<<(1024 * 2048 / 4) / 256, blk>>>(rec_w1, rec_w1r, 1024 * 2048 / 4);
    round_kernel<<<(B * 4096 / 4) / 256, blk>>>(x, xr, B * 4096 / 4);

    // ---- layer 0: in=4096, hid=2048 ----
    prec2_kernel<<<4096 / 256, blk>>>(lp0, pr2, 4096);
    gemm_tf32<true, 0><<<dim3(2048 / 128, B / 128), blk, SM_BT>>>(
        xr, rec_w0r, rec_b0, nullptr, nullptr, pre, B, 2048, 4096);
    ln_kernel<2048><<<B, blk>>>(pre, h0, h0r, ln_g0, ln_b0);
    for (int it = 0; it < 3; it++) {
        gemm_tf32<true, 1><<<dim3(4096 / 128, B / 128), blk, SM_BT>>>(
            h0r, gen_w0r, gen_b0, x, pr2, err, B, 4096, 2048);
        gemm_tf32<false, 2><<<dim3(2048 / 128, B / 128), blk, SM_NN>>>(
            err, gen_w0r, nullptr, h0, nullptr, pre, B, 2048, 4096);
        ln_kernel<2048><<<B, blk>>>(pre, h0, h0r, ln_g0, ln_b0);
    }

    // ---- layer 1: in=2048, hid=1024 ----
    prec2_kernel<<<2048 / 256, blk>>>(lp1, pr2, 2048);
    gemm_tf32<true, 0><<<dim3(1024 / 128, B / 128), blk, SM_BT>>>(
        h0r, rec_w1r, rec_b1, nullptr, nullptr, pre, B, 1024, 2048);
    ln_kernel<1024><<<B, blk>>>(pre, out, h1r, ln_g1, ln_b1);
    for (int it = 0; it < 3; it++) {
        gemm_tf32<true, 1><<<dim3(2048 / 128, B / 128), blk, SM_BT>>>(
            h1r, gen_w1r, gen_b1, h0, pr2, err, B, 2048, 1024);
        gemm_tf32<false, 2><<<dim3(1024 / 128, B / 128), blk, SM_NN>>>(
            err, gen_w1r, nullptr, out, nullptr, pre, B, 1024, 2048);
        ln_kernel<1024><<<B, blk>>>(pre, out, h1r, ln_g1, ln_b1);
    }
}

// round 17
// speedup vs baseline: 1.0812x; 1.0441x over previous
#include <cuda_runtime.h>
#include <cstdint>
#include <math.h>

// ---------------------------------------------------------------------------
// Scratch (static device globals — no runtime allocation)
// ---------------------------------------------------------------------------
__device__ float g_h0 [8192u * 2048u];   // layer0 h, full precision (normal)
__device__ float g_h0r[8192u * 2048u];   // layer0 h, tf32-rounded, K-interleaved
__device__ float g_h1r[8192u * 1024u];   // layer1 h, tf32-rounded, K-interleaved
__device__ float g_pre[8192u * 2048u];   // pre-LN buffer (normal)
__device__ float g_err[8192u * 4096u];   // error, rounded, K-interleaved
__device__ float g_xr [8192u * 4096u];   // x, rounded, K-interleaved
__device__ float g_wts[30u * 1024u * 1024u]; // rounded (+permuted) weights
__device__ float g_prec2[4096];

#define W_GEN0   0u                       // gen_w0  [4096,2048], K-interleaved cols
#define W_REC0   (8u*1024u*1024u)         // rec_w0  [2048,4096], K-interleaved cols
#define W_GEN1   (16u*1024u*1024u)        // gen_w1  [2048,1024], K-interleaved cols
#define W_REC1   (18u*1024u*1024u)        // rec_w1  [1024,2048], K-interleaved cols
#define W_GEN0NN (20u*1024u*1024u)        // gen_w0 row-interleaved [4096,2048]
#define W_GEN1NN (28u*1024u*1024u)        // gen_w1 row-interleaved [2048,1024]

// ---------------------------------------------------------------------------
// Helpers
// ---------------------------------------------------------------------------
__device__ __forceinline__ uint32_t f2tf32(float x) {
    uint32_t r;
    asm("cvt.rna.tf32.f32 %0, %1;" : "=r"(r) : "f"(x));
    return r;
}
__device__ __forceinline__ float roundtf(float x) { return __uint_as_float(f2tf32(x)); }

// K-interleave within 8-groups: u<4 -> 2u ; u>=4 -> 2u-7
__device__ __forceinline__ int kperm(int c) {
    int u = c & 7;
    return (c & ~7) | ((u < 4) ? (2 * u) : (2 * u - 7));
}

__device__ __forceinline__ void mma_tf32(float* c, const uint32_t* a, const uint32_t* b) {
    asm volatile(
        "mma.sync.aligned.m16n8k8.row.col.f32.tf32.tf32.f32 "
        "{%0,%1,%2,%3}, {%4,%5,%6,%7}, {%8,%9}, {%0,%1,%2,%3};\n"
        : "+f"(c[0]), "+f"(c[1]), "+f"(c[2]), "+f"(c[3])
        : "r"(a[0]), "r"(a[1]), "r"(a[2]), "r"(a[3]), "r"(b[0]), "r"(b[1]));
}

__device__ __forceinline__ void cp16(uint32_t dst_smem, const void* src) {
    asm volatile("cp.async.cg.shared.global [%0], [%1], 16;" :: "r"(dst_smem), "l"(src));
}
__device__ __forceinline__ void cp_commit() { asm volatile("cp.async.commit_group;"); }
template <int N>
__device__ __forceinline__ void cp_wait() { asm volatile("cp.async.wait_group %0;" :: "n"(N)); }

// ---------------------------------------------------------------------------
// Round + K-interleave along contiguous dim. n8 = nelems/8, each thread 8 elems.
// stored[8j+2u]=orig[8j+u], stored[8j+2u+1]=orig[8j+u+4]
// ---------------------------------------------------------------------------
__global__ void __launch_bounds__(256) round_perm_kernel(
    const float* __restrict__ in, float* __restrict__ out, int n8)
{
    int i = blockIdx.x * blockDim.x + threadIdx.x;
    if (i < n8) {
        float4 a = reinterpret_cast<const float4*>(in)[2 * i];
        float4 b = reinterpret_cast<const float4*>(in)[2 * i + 1];
        float4 o0, o1;
        o0.x = roundtf(a.x); o0.y = roundtf(b.x); o0.z = roundtf(a.y); o0.w = roundtf(b.y);
        o1.x = roundtf(a.z); o1.y = roundtf(b.z); o1.z = roundtf(a.w); o1.w = roundtf(b.w);
        reinterpret_cast<float4*>(out)[2 * i]     = o0;
        reinterpret_cast<float4*>(out)[2 * i + 1] = o1;
    }
}

// Round + interleave ROWS within 8-groups: out[rowperm(r)][c] = round(in[r][c])
__global__ void __launch_bounds__(256) rowperm_round_kernel(
    const float* __restrict__ in, float* __restrict__ out, int R, int C4)
{
    int i = blockIdx.x * blockDim.x + threadIdx.x;
    if (i < R * C4) {
        int r = i / C4, cc = i % C4;
        int u = r & 7;
        int rp = (r & ~7) | ((u < 4) ? (2 * u) : (2 * u - 7));
        float4 v = reinterpret_cast<const float4*>(in)[i];
        float4 o;
        o.x = roundtf(v.x); o.y = roundtf(v.y);
        o.z = roundtf(v.z); o.w = roundtf(v.w);
        reinterpret_cast<float4*>(out)[(size_t)rp * C4 + cc] = o;
    }
}

// ---------------------------------------------------------------------------
// prec2 = softplus(log_prec)^2
// ---------------------------------------------------------------------------
__global__ void prec2_kernel(const float* __restrict__ lp, float* __restrict__ out, int n) {
    int i = blockIdx.x * blockDim.x + threadIdx.x;
    if (i < n) {
        float v = lp[i];
        float sp = (v > 20.f) ? v : log1pf(expf(v));
        out[i] = sp * sp;
    }
}

// ---------------------------------------------------------------------------
// Row LayerNorm. dst = normal layout; dstr = tf32-rounded, K-interleaved.
// Each thread handles 8 contiguous elements (threads >= H/8 idle in body).
// ---------------------------------------------------------------------------
template <int H>
__global__ void __launch_bounds__(256) ln_kernel(
    const float* __restrict__ src, float* __restrict__ dst, float* __restrict__ dstr,
    const float* __restrict__ gam, const float* __restrict__ bet)
{
    constexpr int G = H / 8;    // 256 (H=2048) or 128 (H=1024)
    int row = blockIdx.x;
    int t = threadIdx.x;
    const float4* s4 = reinterpret_cast<const float4*>(src + (size_t)row * H);
    float4* d4  = reinterpret_cast<float4*>(dst  + (size_t)row * H);
    float4* dr4 = reinterpret_cast<float4*>(dstr + (size_t)row * H);

    float4 a = make_float4(0.f, 0.f, 0.f, 0.f), b = a;
    float sum = 0.f, sq = 0.f;
    if (t < G) {
        a = s4[2 * t]; b = s4[2 * t + 1];
        sum = a.x + a.y + a.z + a.w + b.x + b.y + b.z + b.w;
        sq  = a.x * a.x + a.y * a.y + a.z * a.z + a.w * a.w
            + b.x * b.x + b.y * b.y + b.z * b.z + b.w * b.w;
    }
#pragma unroll
    for (int o = 16; o > 0; o >>= 1) {
        sum += __shfl_xor_sync(0xffffffffu, sum, o);
        sq  += __shfl_xor_sync(0xffffffffu, sq,  o);
    }
    __shared__ float sS[8], sQ[8];
    int w = t >> 5, l = t & 31;
    if (l == 0) { sS[w] = sum; sQ[w] = sq; }
    __syncthreads();
    if (t == 0) {
        float ts = 0.f, tq = 0.f;
#pragma unroll
        for (int i = 0; i < 8; i++) { ts += sS[i]; tq += sQ[i]; }
        sS[0] = ts; sQ[0] = tq;
    }
    __syncthreads();
    float mu  = sS[0] * (1.f / H);
    float var = sQ[0] * (1.f / H) - mu * mu;
    float inv = rsqrtf(var + 1e-5f);

    if (t < G) {
        const float4* g4 = reinterpret_cast<const float4*>(gam);
        const float4* b4 = reinterpret_cast<const float4*>(bet);
        float4 ga = g4[2 * t], gb = g4[2 * t + 1];
        float4 ba = b4[2 * t], bb = b4[2 * t + 1];
        float4 oa, ob;
        oa.x = (a.x - mu) * inv * ga.x + ba.x;
        oa.y = (a.y - mu) * inv * ga.y + ba.y;
        oa.z = (a.z - mu) * inv * ga.z + ba.z;
        oa.w = (a.w - mu) * inv * ga.w + ba.w;
        ob.x = (b.x - mu) * inv * gb.x + bb.x;
        ob.y = (b.y - mu) * inv * gb.y + bb.y;
        ob.z = (b.z - mu) * inv * gb.z + bb.z;
        ob.w = (b.w - mu) * inv * gb.w + bb.w;
        d4[2 * t] = oa; d4[2 * t + 1] = ob;
        float4 r0, r1;   // K-interleaved rounded copy
        r0.x = roundtf(oa.x); r0.y = roundtf(ob.x); r0.z = roundtf(oa.y); r0.w = roundtf(ob.y);
        r1.x = roundtf(oa.z); r1.y = roundtf(ob.z); r1.z = roundtf(oa.w); r1.w = roundtf(ob.w);
        dr4[2 * t] = r0; dr4[2 * t + 1] = r1;
    }
}

// ---------------------------------------------------------------------------
// TF32 mma.sync GEMM, 128x128 tile, 64x32 warp tiles, BK=32, S=2 cp.async
// pipeline. All operands K-interleaved -> LDS.64 fragment loads.
//   BT=true : B(k,n) = W[n,k]   (W row-major [N,K], K-interleaved cols)
//   BT=false: B(k,n) = W[k,n]   (W row-major [K,N], interleaved rows)
// MODE 0: out = acc + bias[n]                          (normal store)
// MODE 1: out = roundtf((X - (acc+bias))*prec2)        (K-interleaved store)
// MODE 2: out = X + 0.2f * acc                         (normal store)
// ---------------------------------------------------------------------------
template <bool BT, int MODE>
__global__ void __launch_bounds__(256, 2) gemm_tf32(
    const float* __restrict__ A, const float* __restrict__ W,
    const float* __restrict__ bias, const float* __restrict__ X,
    const float* __restrict__ prec2, float* __restrict__ OUT,
    int M, int N, int K)
{
    constexpr int AROW = 40;     // 32 k-floats + 8 pad; stride%32==8 -> LDS.64 ok
    constexpr int BRN  = 132;    // NN path: 128 n-floats + 4 pad; %16==4 -> ok
    constexpr int A_FLOATS = 128 * AROW;            // 5120 per stage
    constexpr int B_FLOATS = BT ? 128 * AROW : 32 * BRN;   // 5120 / 4224

    extern __shared__ float sm[];
    float* Asm = sm;                       // [2][128][AROW]
    float* Bsm = sm + 2 * A_FLOATS;

    const uint32_t sA = (uint32_t)__cvta_generic_to_shared(Asm);
    const uint32_t sB = (uint32_t)__cvta_generic_to_shared(Bsm);

    const int tid  = threadIdx.x;
    const int lane = tid & 31;
    const int warp = tid >> 5;
    const int wm = warp >> 2;
    const int wn = warp & 3;
    const int gid = lane >> 2, tig = lane & 3;
    const int M0 = blockIdx.y * 128, N0 = blockIdx.x * 128;

    float acc[4][4][4];
#pragma unroll
    for (int i = 0; i < 4; i++)
#pragma unroll
        for (int j = 0; j < 4; j++)
#pragma unroll
            for (int k = 0; k < 4; k++) acc[i][j][k] = 0.f;

    const int KT = K / 32;

    auto ldgsts = [&](int kt, int st) {
#pragma unroll
        for (int i = 0; i < 4; i++) {
            int c   = tid + 256 * i;           // 0..1023
            int row = c >> 3, kv = c & 7;
            cp16(sA + (uint32_t)(st * A_FLOATS + row * AROW + kv * 4) * 4u,
                 A + (size_t)(M0 + row) * K + kt * 32 + kv * 4);
        }
        if (BT) {
#pragma unroll
            for (int i = 0; i < 4; i++) {
                int c   = tid + 256 * i;
                int row = c >> 3, kv = c & 7;
                cp16(sB + (uint32_t)(st * B_FLOATS + row * AROW + kv * 4) * 4u,
                     W + (size_t)(N0 + row) * K + kt * 32 + kv * 4);
            }
        } else {
#pragma unroll
            for (int i = 0; i < 4; i++) {
                int c  = tid + 256 * i;
                int kr = c >> 5, nv = c & 31;  // stored k-row 0..31, nvec 0..31
                cp16(sB + (uint32_t)(st * B_FLOATS + kr * BRN + nv * 4) * 4u,
                     W + (size_t)(kt * 32 + kr) * N + N0 + nv * 4);
            }
        }
    };

    // prologue: stage 0
    ldgsts(0, 0); cp_commit();

    for (int kt = 0; kt < KT; kt++) {
        cp_wait<0>();
        __syncthreads();

        if (kt + 1 < KT) ldgsts(kt + 1, (kt + 1) & 1);
        cp_commit();

        const int st = kt & 1;
        const uint2* Ast2 = (const uint2*)(Asm + st * A_FLOATS);
        const uint2* Bst2 = (const uint2*)(Bsm + st * B_FLOATS);
        const uint32_t* BstN = (const uint32_t*)(Bsm + st * B_FLOATS);

#pragma unroll
        for (int ks = 0; ks < 4; ks++) {
            uint32_t af[4][4], bf[4][2];
#pragma unroll
            for (int mm = 0; mm < 4; mm++) {
                int r = wm * 64 + mm * 16 + gid;
                uint2 v0 = Ast2[(r    ) * 20 + ks * 4 + tig];   // {k=t, k=t+4}
                uint2 v1 = Ast2[(r + 8) * 20 + ks * 4 + tig];
                af[mm][0] = v0.x; af[mm][2] = v0.y;
                af[mm][1] = v1.x; af[mm][3] = v1.y;
            }
#pragma unroll
            for (int nn = 0; nn < 4; nn++) {
                int cN = wn * 32 + nn * 8 + gid;
                if (BT) {
                    uint2 v = Bst2[cN * 20 + ks * 4 + tig];
                    bf[nn][0] = v.x; bf[nn][1] = v.y;
                } else {
                    bf[nn][0] = BstN[(ks * 8 + 2 * tig    ) * BRN + cN];
                    bf[nn][1] = BstN[(ks * 8 + 2 * tig + 1) * BRN + cN];
                }
            }
#pragma unroll
            for (int mm = 0; mm < 4; mm++)
#pragma unroll
                for (int nn = 0; nn < 4; nn++)
                    mma_tf32(acc[mm][nn], af[mm], bf[nn]);
        }
    }

    // epilogue
#pragma unroll
    for (int mm = 0; mm < 4; mm++) {
        int r0 = M0 + wm * 64 + mm * 16 + gid;
#pragma unroll
        for (int nn = 0; nn < 4; nn++) {
            int c = N0 + wn * 32 + nn * 8 + 2 * tig;
#pragma unroll
            for (int h = 0; h < 2; h++) {
                int r = r0 + h * 8;
                size_t rowoff = (size_t)r * N;
                float v0 = acc[mm][nn][2 * h + 0];
                float v1 = acc[mm][nn][2 * h + 1];
                if (MODE == 0) {
                    v0 += bias[c];
                    v1 += bias[c + 1];
                    float2 o; o.x = v0; o.y = v1;
                    *(float2*)(OUT + rowoff + c) = o;
                } else if (MODE == 1) {
                    float2 xv = *(const float2*)(X + rowoff + c);
                    v0 = roundtf((xv.x - (v0 + bias[c]))     * prec2[c]);
                    v1 = roundtf((xv.y - (v1 + bias[c + 1])) * prec2[c + 1]);
                    OUT[rowoff + kperm(c)]     = v0;   // K-interleaved store
                    OUT[rowoff + kperm(c + 1)] = v1;
                } else {
                    float2 xv = *(const float2*)(X + rowoff + c);
                    v0 = xv.x + 0.2f * v0;
                    v1 = xv.y + 0.2f * v1;
                    float2 o; o.x = v0; o.y = v1;
                    *(float2*)(OUT + rowoff + c) = o;
                }
            }
        }
    }
}

// ---------------------------------------------------------------------------
// Launch sequence (graph-capturable: kernel launches only)
// ---------------------------------------------------------------------------
extern "C" void kernel_launch(void* const* d_in, const int* in_sizes, int n_in,
                              void* d_out, int out_size)
{
    const float* x      = (const float*)d_in[0];
    const float* gen_w0 = (const float*)d_in[1];
    const float* gen_b0 = (const float*)d_in[2];
    const float* rec_w0 = (const float*)d_in[3];
    const float* rec_b0 = (const float*)d_in[4];
    const float* lp0    = (const float*)d_in[5];
    const float* ln_g0  = (const float*)d_in[6];
    const float* ln_b0  = (const float*)d_in[7];
    const float* gen_w1 = (const float*)d_in[8];
    const float* gen_b1 = (const float*)d_in[9];
    const float* rec_w1 = (const float*)d_in[10];
    const float* rec_b1 = (const float*)d_in[11];
    const float* lp1    = (const float*)d_in[12];
    const float* ln_g1  = (const float*)d_in[13];
    const float* ln_b1  = (const float*)d_in[14];
    float* out = (float*)d_out;

    float *h0, *h0r, *h1r, *pre, *err, *xr, *wts, *pr2;
    cudaGetSymbolAddress((void**)&h0,  g_h0);
    cudaGetSymbolAddress((void**)&h0r, g_h0r);
    cudaGetSymbolAddress((void**)&h1r, g_h1r);
    cudaGetSymbolAddress((void**)&pre, g_pre);
    cudaGetSymbolAddress((void**)&err, g_err);
    cudaGetSymbolAddress((void**)&xr,  g_xr);
    cudaGetSymbolAddress((void**)&wts, g_wts);
    cudaGetSymbolAddress((void**)&pr2, g_prec2);

    float* gen_w0r  = wts + W_GEN0;
    float* rec_w0r  = wts + W_REC0;
    float* gen_w1r  = wts + W_GEN1;
    float* rec_w1r  = wts + W_REC1;
    float* gen_w0nn = wts + W_GEN0NN;
    float* gen_w1nn = wts + W_GEN1NN;

    // dynamic smem: BT = 2*(5120*2)*4 = 81,920 B; NN = 2*(5120+4224)*4 = 74,752 B
    const int SM_BT = 2 * (128 * 40 * 2) * 4;
    const int SM_NN = 2 * (128 * 40 + 32 * 132) * 4;
    cudaFuncSetAttribute(gemm_tf32<true, 0>,  cudaFuncAttributeMaxDynamicSharedMemorySize, SM_BT);
    cudaFuncSetAttribute(gemm_tf32<true, 1>,  cudaFuncAttributeMaxDynamicSharedMemorySize, SM_BT);
    cudaFuncSetAttribute(gemm_tf32<false, 2>, cudaFuncAttributeMaxDynamicSharedMemorySize, SM_NN);

    const int B = 8192;
    dim3 blk(256);

    // one-time weight/x prep: round + interleave (values identical to cvt-on-load)
    round_perm_kernel<<<(4096 * 2048 / 8) / 256, blk>>>(gen_w0, gen_w0r, 4096 * 2048 / 8);
    round_perm_kernel<<<(2048 * 4096 / 8) / 256, blk>>>(rec_w0, rec_w0r, 2048 * 4096 / 8);
    round_perm_kernel<<<(2048 * 1024 / 8) / 256, blk>>>(gen_w1, gen_w1r, 2048 * 1024 / 8);
    round_perm_kernel<<<(1024 * 2048 / 8) / 256, blk>>>(rec_w1, rec_w1r, 1024 * 2048 / 8);
    round_perm_kernel<<<(B * 4096 / 8) / 256, blk>>>(x, xr, B * 4096 / 8);
    rowperm_round_kernel<<<(4096 * 2048 / 4) / 256, blk>>>(gen_w0, gen_w0nn, 4096, 2048 / 4);
    rowperm_round_kernel<<<(2048 * 1024 / 4) / 256, blk>>>(gen_w1, gen_w1nn, 2048, 1024 / 4);

    // ---- layer 0: in=4096, hid=2048 ----
    prec2_kernel<<<4096 / 256, blk>>>(lp0, pr2, 4096);
    gemm_tf32<true, 0><<<dim3(2048 / 128, B / 128), blk, SM_BT>>>(
        xr, rec_w0r, rec_b0, nullptr, nullptr, pre, B, 2048, 4096);
    ln_kernel<2048><<<B, blk>>>(pre, h0, h0r, ln_g0, ln_b0);
    for (int it = 0; it < 3; it++) {
        gemm_tf32<true, 1><<<dim3(4096 / 128, B / 128), blk, SM_BT>>>(
            h0r, gen_w0r, gen_b0, x, pr2, err, B, 4096, 2048);
        gemm_tf32<false, 2><<<dim3(2048 / 128, B / 128), blk, SM_NN>>>(
            err, gen_w0nn, nullptr, h0, nullptr, pre, B, 2048, 4096);
        ln_kernel<2048><<<B, blk>>>(pre, h0, h0r, ln_g0, ln_b0);
    }

    // ---- layer 1: in=2048, hid=1024 ----
    prec2_kernel<<<2048 / 256, blk>>>(lp1, pr2, 2048);
    gemm_tf32<true, 0><<<dim3(1024 / 128, B / 128), blk, SM_BT>>>(
        h0r, rec_w1r, rec_b1, nullptr, nullptr, pre, B, 1024, 2048);
    ln_kernel<1024><<<B, blk>>>(pre, out, h1r, ln_g1, ln_b1);
    for (int it = 0; it < 3; it++) {
        gemm_tf32<true, 1><<<dim3(2048 / 128, B / 128), blk, SM_BT>>>(
            h1r, gen_w1r, gen_b1, h0, pr2, err, B, 2048, 1024);
        gemm_tf32<false, 2><<<dim3(1024 / 128, B / 128), blk, SM_NN>>>(
            err, gen_w1nn, nullptr, out, nullptr, pre, B, 1024, 2048);
        ln_kernel<1024><<<B, blk>>>(pre, out, h1r, ln_g1, ln_b1);
    }
}